// round 1
// baseline (speedup 1.0000x reference)
#include <cuda_runtime.h>

// ---------------------------------------------------------------------------
// SelfAttention: out = W_O @ ( (W_V x) @ softmax( (W_K x)^T (W_Q x) ) )
// B=4, D=1024, N=2048, MH=MV=1024, fp32 throughout.
// Round 1: generic strided/batched SGEMM (128x128x16 tile, 8x8/thread) + softmax.
// ---------------------------------------------------------------------------

#define BATCH 4
#define DDIM  1024
#define NSEQ  2048
#define MH    1024
#define MV    1024

#define BM 128
#define BN 128
#define BK 16
#define TM 8
#define TN 8
// 256 threads per block: (BM/TM)*(BN/TN) = 16*16

// Scratch (allocation-free contract: __device__ globals)
__device__ __align__(256) float g_q[(size_t)BATCH * MH * NSEQ];
__device__ __align__(256) float g_k[(size_t)BATCH * MH * NSEQ];
__device__ __align__(256) float g_v[(size_t)BATCH * MV * NSEQ];
__device__ __align__(256) float g_s[(size_t)BATCH * NSEQ * NSEQ];
__device__ __align__(256) float g_attn[(size_t)BATCH * MV * NSEQ];

// C[m,n] = sum_k A_elem(m,k) * B_elem(k,n)
//   A_K_CONTIG=true :  A(m,k) = A[m*sAm + k]         (k contiguous)
//   A_K_CONTIG=false:  A(m,k) = A[k*sAk + m]         (m contiguous)
//   B(k,n) = B[k*sBk + n]  (n contiguous always)
//   C row-major [M,N]. blockIdx.z batches with element strides batchA/B/C.
template <bool A_K_CONTIG>
__global__ void __launch_bounds__(256)
gemm_kernel(const float* __restrict__ A, const float* __restrict__ B,
            float* __restrict__ C,
            int M, int N, int K,
            long long sAm, long long sAk, long long sBk,
            long long batchA, long long batchB, long long batchC)
{
    __shared__ __align__(16) float As[BK][BM + 4];
    __shared__ __align__(16) float Bs[BK][BN];

    const float* Ab = A + (long long)blockIdx.z * batchA;
    const float* Bb = B + (long long)blockIdx.z * batchB;
    float*       Cb = C + (long long)blockIdx.z * batchC;

    const int bm  = blockIdx.y * BM;
    const int bn  = blockIdx.x * BN;
    const int tid = threadIdx.x;

    const int tm = (tid >> 4) * TM;   // 0..120
    const int tn = (tid & 15) * TN;   // 0..120

    float acc[TM][TN];
#pragma unroll
    for (int i = 0; i < TM; i++)
#pragma unroll
        for (int j = 0; j < TN; j++) acc[i][j] = 0.0f;

    for (int k0 = 0; k0 < K; k0 += BK) {
        // ---- load A tile into As[k][m] (transposed for m-contiguous reads) ----
        if (A_K_CONTIG) {
            // 128x16 tile; thread loads 2 float4 along k
#pragma unroll
            for (int i = 0; i < 2; i++) {
                int idx = tid + i * 256;       // float4 index 0..511
                int m   = idx >> 2;            // 0..127
                int kk  = (idx & 3) * 4;       // 0,4,8,12
                float4 vv = *reinterpret_cast<const float4*>(
                    Ab + (long long)(bm + m) * sAm + (k0 + kk));
                As[kk + 0][m] = vv.x;
                As[kk + 1][m] = vv.y;
                As[kk + 2][m] = vv.z;
                As[kk + 3][m] = vv.w;
            }
        } else {
            // m-contiguous: direct float4 into As rows
#pragma unroll
            for (int i = 0; i < 2; i++) {
                int idx = tid + i * 256;
                int kk  = idx >> 5;            // 0..15
                int m4  = (idx & 31) * 4;      // 0..124
                float4 vv = *reinterpret_cast<const float4*>(
                    Ab + (long long)(k0 + kk) * sAk + (bm + m4));
                *reinterpret_cast<float4*>(&As[kk][m4]) = vv;
            }
        }
        // ---- load B tile Bs[k][n] ----
#pragma unroll
        for (int i = 0; i < 2; i++) {
            int idx = tid + i * 256;
            int kk  = idx >> 5;
            int n4  = (idx & 31) * 4;
            float4 vv = *reinterpret_cast<const float4*>(
                Bb + (long long)(k0 + kk) * sBk + (bn + n4));
            *reinterpret_cast<float4*>(&Bs[kk][n4]) = vv;
        }
        __syncthreads();

        // ---- compute ----
#pragma unroll
        for (int kk = 0; kk < BK; kk++) {
            float4 a0 = *reinterpret_cast<const float4*>(&As[kk][tm]);
            float4 a1 = *reinterpret_cast<const float4*>(&As[kk][tm + 4]);
            float4 b0 = *reinterpret_cast<const float4*>(&Bs[kk][tn]);
            float4 b1 = *reinterpret_cast<const float4*>(&Bs[kk][tn + 4]);
            float ar[TM] = {a0.x, a0.y, a0.z, a0.w, a1.x, a1.y, a1.z, a1.w};
            float br[TN] = {b0.x, b0.y, b0.z, b0.w, b1.x, b1.y, b1.z, b1.w};
#pragma unroll
            for (int i = 0; i < TM; i++)
#pragma unroll
                for (int j = 0; j < TN; j++)
                    acc[i][j] = fmaf(ar[i], br[j], acc[i][j]);
        }
        __syncthreads();
    }

    // ---- store ----
#pragma unroll
    for (int i = 0; i < TM; i++) {
        float4* cp = reinterpret_cast<float4*>(
            Cb + (long long)(bm + tm + i) * N + (bn + tn));
        cp[0] = make_float4(acc[i][0], acc[i][1], acc[i][2], acc[i][3]);
        cp[1] = make_float4(acc[i][4], acc[i][5], acc[i][6], acc[i][7]);
    }
}

// Row softmax over last dim; one block (256 thr) per row.
__global__ void __launch_bounds__(256)
softmax_kernel(float* __restrict__ S, int N)
{
    float* row = S + (long long)blockIdx.x * N;
    const int tid = threadIdx.x;
    __shared__ float red[256];

    float m = -3.4e38f;
    for (int j = tid; j < N; j += 256) m = fmaxf(m, row[j]);
    red[tid] = m;
    __syncthreads();
    for (int s = 128; s > 0; s >>= 1) {
        if (tid < s) red[tid] = fmaxf(red[tid], red[tid + s]);
        __syncthreads();
    }
    m = red[0];
    __syncthreads();

    float sum = 0.0f;
    for (int j = tid; j < N; j += 256) {
        float e = __expf(row[j] - m);
        row[j] = e;
        sum += e;
    }
    red[tid] = sum;
    __syncthreads();
    for (int s = 128; s > 0; s >>= 1) {
        if (tid < s) red[tid] += red[tid + s];
        __syncthreads();
    }
    float inv = 1.0f / red[0];
    __syncthreads();
    for (int j = tid; j < N; j += 256) row[j] *= inv;
}

extern "C" void kernel_launch(void* const* d_in, const int* in_sizes, int n_in,
                              void* d_out, int out_size)
{
    const float* x   = (const float*)d_in[0];  // [B, D, N]
    const float* W_Q = (const float*)d_in[1];  // [MH, D]
    const float* W_K = (const float*)d_in[2];  // [MH, D]
    const float* W_V = (const float*)d_in[3];  // [MV, D]
    const float* W_O = (const float*)d_in[4];  // [D, MV]
    float*       out = (float*)d_out;          // [B, D, N]

    float *q, *k, *v, *s, *attn;
    cudaGetSymbolAddress((void**)&q,    g_q);
    cudaGetSymbolAddress((void**)&k,    g_k);
    cudaGetSymbolAddress((void**)&v,    g_v);
    cudaGetSymbolAddress((void**)&s,    g_s);
    cudaGetSymbolAddress((void**)&attn, g_attn);

    const long long xB  = (long long)DDIM * NSEQ;   // x batch stride
    const long long pB  = (long long)MH   * NSEQ;   // proj batch stride
    const long long sB  = (long long)NSEQ * NSEQ;   // scores batch stride

    // --- QKV projections: C[m,n] = sum_d W[m,d] * x_b[d,n] ---
    {
        dim3 grid(NSEQ / BN, MH / BM, BATCH);
        gemm_kernel<true><<<grid, 256>>>(W_Q, x, q, MH, NSEQ, DDIM,
                                         DDIM, 1, NSEQ, 0, xB, pB);
        gemm_kernel<true><<<grid, 256>>>(W_K, x, k, MH, NSEQ, DDIM,
                                         DDIM, 1, NSEQ, 0, xB, pB);
        gemm_kernel<true><<<grid, 256>>>(W_V, x, v, MV, NSEQ, DDIM,
                                         DDIM, 1, NSEQ, 0, xB, pB);
    }

    // --- scores[i,j] = sum_h k[h,i] * q[h,j]  (A m-contiguous, sAk = NSEQ) ---
    {
        dim3 grid(NSEQ / BN, NSEQ / BM, BATCH);
        gemm_kernel<false><<<grid, 256>>>(k, q, s, NSEQ, NSEQ, MH,
                                          1, NSEQ, NSEQ, pB, pB, sB);
    }

    // --- softmax over last dim ---
    softmax_kernel<<<BATCH * NSEQ, 256>>>(s, NSEQ);

    // --- attn[v,j] = sum_i V[v,i] * S[i,j] ---
    {
        dim3 grid(NSEQ / BN, MV / BM, BATCH);
        gemm_kernel<true><<<grid, 256>>>(v, s, attn, MV, NSEQ, NSEQ,
                                         NSEQ, 1, NSEQ, pB, sB, pB);
    }

    // --- out[d,j] = sum_v W_O[d,v] * attn[v,j] ---
    {
        dim3 grid(NSEQ / BN, DDIM / BM, BATCH);
        gemm_kernel<true><<<grid, 256>>>(W_O, attn, out, DDIM, NSEQ, MV,
                                         MV, 1, NSEQ, 0, pB, xB);
    }
}

// round 3
// speedup vs baseline: 1.1881x; 1.1881x over previous
#include <cuda_runtime.h>
#include <cstdint>

// ---------------------------------------------------------------------------
// SelfAttention on GB300 (sm_103 base target): all 5 GEMMs via legacy
// mma.sync.m16n8k8 tf32 with 2-term TF32 split (3 products) ~= fp32 accuracy.
// ---------------------------------------------------------------------------

#define BATCH 4
#define DDIM  1024
#define NSEQ  2048
#define MH    1024
#define MV    1024

// Scratch (allocation-free contract: __device__ globals)
__device__ __align__(256) float g_q[(size_t)BATCH * MH * NSEQ];
__device__ __align__(256) float g_k[(size_t)BATCH * MH * NSEQ];
__device__ __align__(256) float g_v[(size_t)BATCH * MV * NSEQ];
__device__ __align__(256) float g_s[(size_t)BATCH * NSEQ * NSEQ];
__device__ __align__(256) float g_attn[(size_t)BATCH * MV * NSEQ];

// ---- smem layout (float offsets) ----
#define PA 36     // A pitch (floats): frag banks 4r+c -> conflict-free
#define PB 136    // B pitch (floats): frag banks 8t+g -> conflict-free
#define OF_AHI 0
#define OF_ALO (128 * PA)            // 4608
#define OF_BHI (2 * 128 * PA)        // 9216
#define OF_BLO (OF_BHI + 32 * PB)    // 13568
#define OF_STG (OF_BLO + 32 * PB)    // 17920
#define SMEM_FLOATS (OF_STG + 32 * 128)   // 22016 -> 88064 B

__device__ __forceinline__ void split2u(float x, uint32_t& h, uint32_t& l) {
    asm("cvt.rna.tf32.f32 %0, %1;" : "=r"(h) : "f"(x));
    float r = x - __uint_as_float(h);
    asm("cvt.rna.tf32.f32 %0, %1;" : "=r"(l) : "f"(r));
}

__device__ __forceinline__ void mma_tf32(float* c, const uint32_t* a, const uint32_t* b) {
    asm volatile(
        "mma.sync.aligned.m16n8k8.row.col.f32.tf32.tf32.f32 "
        "{%0,%1,%2,%3}, {%4,%5,%6,%7}, {%8,%9}, {%0,%1,%2,%3};"
        : "+f"(c[0]), "+f"(c[1]), "+f"(c[2]), "+f"(c[3])
        : "r"(a[0]), "r"(a[1]), "r"(a[2]), "r"(a[3]), "r"(b[0]), "r"(b[1]));
}

// ---------------------------------------------------------------------------
// C[m,n] = sum_k Aelem(m,k) * B[k*sBk + n]
//   TRANS_A=false: Aelem(m,k) = A[m*sA + k]    (k contiguous)
//   TRANS_A=true : Aelem(m,k) = A[k*sA + m]    (m contiguous; smem transpose)
// Tile 128x128x32, 256 threads (8 warps, warp tile 64x32).
// ---------------------------------------------------------------------------
template <bool TRANS_A>
__global__ void __launch_bounds__(256, 1)
gemm_mma(const float* __restrict__ A, const float* __restrict__ B, float* __restrict__ C,
         int K, long long sA, long long sBk, long long ldC,
         long long bA, long long bB, long long bC)
{
    extern __shared__ float sm[];
    float* Ahi = sm + OF_AHI;
    float* Alo = sm + OF_ALO;
    float* Bhi = sm + OF_BHI;
    float* Blo = sm + OF_BLO;
    float* Stg = sm + OF_STG;

    const int tid = threadIdx.x, wid = tid >> 5, lane = tid & 31;
    const int gid = lane >> 2, tig = lane & 3;   // group id / thread-in-group
    const int wm = (wid >> 2) << 6;              // warp m offset: 0 or 64
    const int wn = (wid & 3) << 5;               // warp n offset: 0,32,64,96

    const float* Ab = A + (long long)blockIdx.z * bA;
    const float* Bb = B + (long long)blockIdx.z * bB;
    float*       Cb = C + (long long)blockIdx.z * bC;
    const long long bm = (long long)blockIdx.y << 7;
    const long long bn = (long long)blockIdx.x << 7;

    float acc[4][4][4];
#pragma unroll
    for (int mt = 0; mt < 4; mt++)
#pragma unroll
        for (int nt = 0; nt < 4; nt++)
#pragma unroll
            for (int r = 0; r < 4; r++) acc[mt][nt][r] = 0.0f;

    for (int k0 = 0; k0 < K; k0 += 32) {
        // ---------- load B tile [32 x 128] (n contiguous) ----------
#pragma unroll
        for (int i = 0; i < 4; i++) {
            int idx = tid + (i << 8);                 // f4 idx 0..1023
            int kk = idx >> 5, n4 = (idx & 31) << 2;
            float4 v = *reinterpret_cast<const float4*>(Bb + (long long)(k0 + kk) * sBk + bn + n4);
            uint32_t h0,l0,h1,l1,h2,l2,h3,l3;
            split2u(v.x,h0,l0); split2u(v.y,h1,l1); split2u(v.z,h2,l2); split2u(v.w,h3,l3);
            float4 fh = make_float4(__uint_as_float(h0),__uint_as_float(h1),__uint_as_float(h2),__uint_as_float(h3));
            float4 fl = make_float4(__uint_as_float(l0),__uint_as_float(l1),__uint_as_float(l2),__uint_as_float(l3));
            *reinterpret_cast<float4*>(Bhi + kk * PB + n4) = fh;
            *reinterpret_cast<float4*>(Blo + kk * PB + n4) = fl;
        }
        // ---------- load A tile ----------
        if (!TRANS_A) {
            // [128 m rows][32 k] k-contiguous
#pragma unroll
            for (int i = 0; i < 4; i++) {
                int idx = tid + (i << 8);
                int m = idx >> 3, k4 = (idx & 7) << 2;
                float4 v = *reinterpret_cast<const float4*>(Ab + (long long)(bm + m) * sA + k0 + k4);
                uint32_t h0,l0,h1,l1,h2,l2,h3,l3;
                split2u(v.x,h0,l0); split2u(v.y,h1,l1); split2u(v.z,h2,l2); split2u(v.w,h3,l3);
                float4 fh = make_float4(__uint_as_float(h0),__uint_as_float(h1),__uint_as_float(h2),__uint_as_float(h3));
                float4 fl = make_float4(__uint_as_float(l0),__uint_as_float(l1),__uint_as_float(l2),__uint_as_float(l3));
                *reinterpret_cast<float4*>(Ahi + m * PA + k4) = fh;
                *reinterpret_cast<float4*>(Alo + m * PA + k4) = fl;
            }
            __syncthreads();
        } else {
            // source slab [32 k rows][128 m] m-contiguous -> stage -> transpose
#pragma unroll
            for (int i = 0; i < 4; i++) {
                int idx = tid + (i << 8);
                int kk = idx >> 5, m4 = (idx & 31) << 2;
                float4 v = *reinterpret_cast<const float4*>(Ab + (long long)(k0 + kk) * sA + bm + m4);
                *reinterpret_cast<float4*>(Stg + kk * 128 + m4) = v;
            }
            __syncthreads();
            {
                const int m = tid & 127, kh = (tid >> 7) << 4;   // 16 k per thread
#pragma unroll
                for (int g = 0; g < 4; g++) {
                    uint32_t h[4], l[4];
#pragma unroll
                    for (int j = 0; j < 4; j++)
                        split2u(Stg[(kh + g * 4 + j) * 128 + m], h[j], l[j]);
                    float4 fh = make_float4(__uint_as_float(h[0]),__uint_as_float(h[1]),__uint_as_float(h[2]),__uint_as_float(h[3]));
                    float4 fl = make_float4(__uint_as_float(l[0]),__uint_as_float(l[1]),__uint_as_float(l[2]),__uint_as_float(l[3]));
                    *reinterpret_cast<float4*>(Ahi + m * PA + kh + g * 4) = fh;
                    *reinterpret_cast<float4*>(Alo + m * PA + kh + g * 4) = fl;
                }
            }
            __syncthreads();
        }

        // ---------- MMA: 4 k-steps of 8 ----------
#pragma unroll
        for (int ks = 0; ks < 4; ks++) {
            const int kb = ks << 3;
            uint32_t ah[4][4], al[4][4], bh[4][2], bl[4][2];
#pragma unroll
            for (int mt = 0; mt < 4; mt++) {
                int r0 = wm + (mt << 4) + gid;
                int c0 = kb + tig;
                ah[mt][0] = __float_as_uint(Ahi[r0 * PA + c0]);
                ah[mt][1] = __float_as_uint(Ahi[(r0 + 8) * PA + c0]);
                ah[mt][2] = __float_as_uint(Ahi[r0 * PA + c0 + 4]);
                ah[mt][3] = __float_as_uint(Ahi[(r0 + 8) * PA + c0 + 4]);
                al[mt][0] = __float_as_uint(Alo[r0 * PA + c0]);
                al[mt][1] = __float_as_uint(Alo[(r0 + 8) * PA + c0]);
                al[mt][2] = __float_as_uint(Alo[r0 * PA + c0 + 4]);
                al[mt][3] = __float_as_uint(Alo[(r0 + 8) * PA + c0 + 4]);
            }
#pragma unroll
            for (int nt = 0; nt < 4; nt++) {
                int cc = wn + (nt << 3) + gid;
                bh[nt][0] = __float_as_uint(Bhi[(kb + tig) * PB + cc]);
                bh[nt][1] = __float_as_uint(Bhi[(kb + tig + 4) * PB + cc]);
                bl[nt][0] = __float_as_uint(Blo[(kb + tig) * PB + cc]);
                bl[nt][1] = __float_as_uint(Blo[(kb + tig + 4) * PB + cc]);
            }
            // product-major: same-acc mmas are 16 apart (no RAW chain)
#pragma unroll
            for (int mt = 0; mt < 4; mt++)
#pragma unroll
                for (int nt = 0; nt < 4; nt++) mma_tf32(acc[mt][nt], ah[mt], bh[nt]);
#pragma unroll
            for (int mt = 0; mt < 4; mt++)
#pragma unroll
                for (int nt = 0; nt < 4; nt++) mma_tf32(acc[mt][nt], ah[mt], bl[nt]);
#pragma unroll
            for (int mt = 0; mt < 4; mt++)
#pragma unroll
                for (int nt = 0; nt < 4; nt++) mma_tf32(acc[mt][nt], al[mt], bh[nt]);
        }
        __syncthreads();
    }

    // ---------- epilogue: direct float2 stores ----------
#pragma unroll
    for (int mt = 0; mt < 4; mt++) {
        long long r0 = bm + wm + (mt << 4) + gid;
#pragma unroll
        for (int nt = 0; nt < 4; nt++) {
            long long cc = bn + wn + (nt << 3) + (tig << 1);
            *reinterpret_cast<float2*>(Cb + r0 * ldC + cc)       = make_float2(acc[mt][nt][0], acc[mt][nt][1]);
            *reinterpret_cast<float2*>(Cb + (r0 + 8) * ldC + cc) = make_float2(acc[mt][nt][2], acc[mt][nt][3]);
        }
    }
}

// ---------------- softmax over last dim ----------------
__global__ void __launch_bounds__(256)
softmax_kernel(float* __restrict__ S, int N)
{
    float* row = S + (long long)blockIdx.x * N;
    const int tid = threadIdx.x;
    __shared__ float red[256];

    float m = -3.4e38f;
    for (int j = tid; j < N; j += 256) m = fmaxf(m, row[j]);
    red[tid] = m;
    __syncthreads();
    for (int s = 128; s > 0; s >>= 1) {
        if (tid < s) red[tid] = fmaxf(red[tid], red[tid + s]);
        __syncthreads();
    }
    m = red[0];
    __syncthreads();

    float sum = 0.0f;
    for (int j = tid; j < N; j += 256) {
        float e = __expf(row[j] - m);
        row[j] = e;
        sum += e;
    }
    red[tid] = sum;
    __syncthreads();
    for (int s = 128; s > 0; s >>= 1) {
        if (tid < s) red[tid] += red[tid + s];
        __syncthreads();
    }
    float inv = 1.0f / red[0];
    __syncthreads();
    for (int j = tid; j < N; j += 256) row[j] *= inv;
}

extern "C" void kernel_launch(void* const* d_in, const int* in_sizes, int n_in,
                              void* d_out, int out_size)
{
    const float* x   = (const float*)d_in[0];  // [B, D, N]
    const float* W_Q = (const float*)d_in[1];  // [MH, D]
    const float* W_K = (const float*)d_in[2];  // [MH, D]
    const float* W_V = (const float*)d_in[3];  // [MV, D]
    const float* W_O = (const float*)d_in[4];  // [D, MV]
    float*       out = (float*)d_out;          // [B, D, N]

    float *q, *k, *v, *s, *attn;
    cudaGetSymbolAddress((void**)&q,    g_q);
    cudaGetSymbolAddress((void**)&k,    g_k);
    cudaGetSymbolAddress((void**)&v,    g_v);
    cudaGetSymbolAddress((void**)&s,    g_s);
    cudaGetSymbolAddress((void**)&attn, g_attn);

    const size_t smem = SMEM_FLOATS * sizeof(float);
    cudaFuncSetAttribute(gemm_mma<false>, cudaFuncAttributeMaxDynamicSharedMemorySize, (int)smem);
    cudaFuncSetAttribute(gemm_mma<true>,  cudaFuncAttributeMaxDynamicSharedMemorySize, (int)smem);

    const long long xB = (long long)DDIM * NSEQ;
    const long long pB = (long long)MH * NSEQ;
    const long long sB = (long long)NSEQ * NSEQ;

    // Q = W_Q @ x
    {
        dim3 g(NSEQ / 128, MH / 128, BATCH);
        gemm_mma<false><<<g, 256, smem>>>(W_Q, x, q, DDIM, DDIM, NSEQ, NSEQ, 0, xB, pB);
        gemm_mma<false><<<g, 256, smem>>>(W_K, x, k, DDIM, DDIM, NSEQ, NSEQ, 0, xB, pB);
        gemm_mma<false><<<g, 256, smem>>>(W_V, x, v, DDIM, DDIM, NSEQ, NSEQ, 0, xB, pB);
    }
    // scores[i,j] = sum_h k[h,i] * q[h,j]   (A = k, m-contiguous -> TRANS_A)
    {
        dim3 g(NSEQ / 128, NSEQ / 128, BATCH);
        gemm_mma<true><<<g, 256, smem>>>(k, q, s, MH, NSEQ, NSEQ, NSEQ, pB, pB, sB);
    }
    softmax_kernel<<<BATCH * NSEQ, 256>>>(s, NSEQ);
    // attn[v,j] = sum_i V[v,i] * S[i,j]
    {
        dim3 g(NSEQ / 128, MV / 128, BATCH);
        gemm_mma<false><<<g, 256, smem>>>(v, s, attn, NSEQ, NSEQ, NSEQ, NSEQ, pB, sB, pB);
    }
    // out[d,j] = sum_v W_O[d,v] * attn[v,j]
    {
        dim3 g(NSEQ / 128, DDIM / 128, BATCH);
        gemm_mma<false><<<g, 256, smem>>>(W_O, attn, out, MV, MV, NSEQ, NSEQ, 0, pB, xB);
    }
}

// round 4
// speedup vs baseline: 1.3574x; 1.1424x over previous
#include <cuda_runtime.h>
#include <cstdint>

// ---------------------------------------------------------------------------
// SelfAttention on GB300 (sm_103 base target): all 5 GEMMs via legacy
// mma.sync.m16n8k8 tf32 with 2-term TF32 split (3 products) ~= fp32 accuracy.
// R4: CTA tile 128x64, warp tile 32x32 -> <=128 regs -> 2 CTAs/SM (overlap).
// ---------------------------------------------------------------------------

#define BATCH 4
#define DDIM  1024
#define NSEQ  2048
#define MH    1024
#define MV    1024

// Scratch (allocation-free contract: __device__ globals)
__device__ __align__(256) float g_q[(size_t)BATCH * MH * NSEQ];
__device__ __align__(256) float g_k[(size_t)BATCH * MH * NSEQ];
__device__ __align__(256) float g_v[(size_t)BATCH * MV * NSEQ];
__device__ __align__(256) float g_s[(size_t)BATCH * NSEQ * NSEQ];
__device__ __align__(256) float g_attn[(size_t)BATCH * MV * NSEQ];

// ---- smem layout (float offsets) ----
#define PA 36     // A pitch (floats)
#define PB 72     // B pitch (floats): frag banks 8*tig+gid -> conflict-free
#define OF_AHI 0
#define OF_ALO (128 * PA)              // 4608
#define OF_BHI (2 * 128 * PA)          // 9216
#define OF_BLO (OF_BHI + 32 * PB)      // 11520
#define OF_STG (OF_BLO + 32 * PB)      // 13824
#define SMEM_FLOATS (OF_STG + 32 * 128)   // 17920 floats = 71680 B

__device__ __forceinline__ void split2u(float x, uint32_t& h, uint32_t& l) {
    asm("cvt.rna.tf32.f32 %0, %1;" : "=r"(h) : "f"(x));
    float r = x - __uint_as_float(h);
    asm("cvt.rna.tf32.f32 %0, %1;" : "=r"(l) : "f"(r));
}

__device__ __forceinline__ void mma_tf32(float* c, const uint32_t* a, const uint32_t* b) {
    asm volatile(
        "mma.sync.aligned.m16n8k8.row.col.f32.tf32.tf32.f32 "
        "{%0,%1,%2,%3}, {%4,%5,%6,%7}, {%8,%9}, {%0,%1,%2,%3};"
        : "+f"(c[0]), "+f"(c[1]), "+f"(c[2]), "+f"(c[3])
        : "r"(a[0]), "r"(a[1]), "r"(a[2]), "r"(a[3]), "r"(b[0]), "r"(b[1]));
}

// ---------------------------------------------------------------------------
// C[m,n] = sum_k Aelem(m,k) * B[k*sBk + n]
//   TRANS_A=false: Aelem(m,k) = A[m*sA + k]   (k contiguous)
//   TRANS_A=true : Aelem(m,k) = A[k*sA + m]   (m contiguous; smem transpose)
// Tile 128(M) x 64(N) x 32(K). 256 threads = 8 warps, warp tile 32x32.
// ---------------------------------------------------------------------------
template <bool TRANS_A>
__global__ void __launch_bounds__(256, 2)
gemm_mma(const float* __restrict__ A, const float* __restrict__ B, float* __restrict__ C,
         int K, long long sA, long long sBk, long long ldC,
         long long bA, long long bB, long long bC)
{
    extern __shared__ float sm[];
    float* Ahi = sm + OF_AHI;
    float* Alo = sm + OF_ALO;
    float* Bhi = sm + OF_BHI;
    float* Blo = sm + OF_BLO;
    float* Stg = sm + OF_STG;

    const int tid = threadIdx.x, wid = tid >> 5, lane = tid & 31;
    const int gid = lane >> 2, tig = lane & 3;
    const int wm = (wid & 3) << 5;     // 0,32,64,96
    const int wn = (wid >> 2) << 5;    // 0,32

    const float* Ab = A + (long long)blockIdx.z * bA;
    const float* Bb = B + (long long)blockIdx.z * bB;
    float*       Cb = C + (long long)blockIdx.z * bC;
    const long long bm = (long long)blockIdx.y << 7;
    const long long bn = (long long)blockIdx.x << 6;

    float acc[2][4][4];
#pragma unroll
    for (int mt = 0; mt < 2; mt++)
#pragma unroll
        for (int nt = 0; nt < 4; nt++)
#pragma unroll
            for (int r = 0; r < 4; r++) acc[mt][nt][r] = 0.0f;

    for (int k0 = 0; k0 < K; k0 += 32) {
        // ---------- B tile [32 k][64 n] ----------
#pragma unroll
        for (int i = 0; i < 2; i++) {
            int idx = tid + (i << 8);               // f4 idx 0..511
            int kk = idx >> 4, n4 = (idx & 15) << 2;
            float4 v = *reinterpret_cast<const float4*>(Bb + (long long)(k0 + kk) * sBk + bn + n4);
            uint32_t h0,l0,h1,l1,h2,l2,h3,l3;
            split2u(v.x,h0,l0); split2u(v.y,h1,l1); split2u(v.z,h2,l2); split2u(v.w,h3,l3);
            *reinterpret_cast<float4*>(Bhi + kk * PB + n4) =
                make_float4(__uint_as_float(h0),__uint_as_float(h1),__uint_as_float(h2),__uint_as_float(h3));
            *reinterpret_cast<float4*>(Blo + kk * PB + n4) =
                make_float4(__uint_as_float(l0),__uint_as_float(l1),__uint_as_float(l2),__uint_as_float(l3));
        }
        // ---------- A tile [128 m][32 k] ----------
        if (!TRANS_A) {
#pragma unroll
            for (int i = 0; i < 4; i++) {
                int idx = tid + (i << 8);           // f4 idx 0..1023
                int m = idx >> 3, k4 = (idx & 7) << 2;
                float4 v = *reinterpret_cast<const float4*>(Ab + (long long)(bm + m) * sA + k0 + k4);
                uint32_t h0,l0,h1,l1,h2,l2,h3,l3;
                split2u(v.x,h0,l0); split2u(v.y,h1,l1); split2u(v.z,h2,l2); split2u(v.w,h3,l3);
                *reinterpret_cast<float4*>(Ahi + m * PA + k4) =
                    make_float4(__uint_as_float(h0),__uint_as_float(h1),__uint_as_float(h2),__uint_as_float(h3));
                *reinterpret_cast<float4*>(Alo + m * PA + k4) =
                    make_float4(__uint_as_float(l0),__uint_as_float(l1),__uint_as_float(l2),__uint_as_float(l3));
            }
            __syncthreads();
        } else {
            // stage [32 k][128 m] coalesced, then transpose+split
#pragma unroll
            for (int i = 0; i < 4; i++) {
                int idx = tid + (i << 8);
                int kk = idx >> 5, m4 = (idx & 31) << 2;
                float4 v = *reinterpret_cast<const float4*>(Ab + (long long)(k0 + kk) * sA + bm + m4);
                *reinterpret_cast<float4*>(Stg + kk * 128 + m4) = v;
            }
            __syncthreads();
            {
                const int m = tid & 127, kh = (tid >> 7) << 4;   // 16 k per thread
#pragma unroll
                for (int g = 0; g < 4; g++) {
                    uint32_t h[4], l[4];
#pragma unroll
                    for (int j = 0; j < 4; j++)
                        split2u(Stg[(kh + g * 4 + j) * 128 + m], h[j], l[j]);
                    *reinterpret_cast<float4*>(Ahi + m * PA + kh + g * 4) =
                        make_float4(__uint_as_float(h[0]),__uint_as_float(h[1]),__uint_as_float(h[2]),__uint_as_float(h[3]));
                    *reinterpret_cast<float4*>(Alo + m * PA + kh + g * 4) =
                        make_float4(__uint_as_float(l[0]),__uint_as_float(l[1]),__uint_as_float(l[2]),__uint_as_float(l[3]));
                }
            }
            __syncthreads();
        }

        // ---------- MMA: 4 k-steps of 8 ----------
#pragma unroll
        for (int ks = 0; ks < 4; ks++) {
            const int kb = ks << 3;
            uint32_t ah[2][4], al[2][4], bh[4][2], bl[4][2];
#pragma unroll
            for (int mt = 0; mt < 2; mt++) {
                int r0 = wm + (mt << 4) + gid;
                int c0 = kb + tig;
                ah[mt][0] = __float_as_uint(Ahi[r0 * PA + c0]);
                ah[mt][1] = __float_as_uint(Ahi[(r0 + 8) * PA + c0]);
                ah[mt][2] = __float_as_uint(Ahi[r0 * PA + c0 + 4]);
                ah[mt][3] = __float_as_uint(Ahi[(r0 + 8) * PA + c0 + 4]);
                al[mt][0] = __float_as_uint(Alo[r0 * PA + c0]);
                al[mt][1] = __float_as_uint(Alo[(r0 + 8) * PA + c0]);
                al[mt][2] = __float_as_uint(Alo[r0 * PA + c0 + 4]);
                al[mt][3] = __float_as_uint(Alo[(r0 + 8) * PA + c0 + 4]);
            }
#pragma unroll
            for (int nt = 0; nt < 4; nt++) {
                int cc = wn + (nt << 3) + gid;
                bh[nt][0] = __float_as_uint(Bhi[(kb + tig) * PB + cc]);
                bh[nt][1] = __float_as_uint(Bhi[(kb + tig + 4) * PB + cc]);
                bl[nt][0] = __float_as_uint(Blo[(kb + tig) * PB + cc]);
                bl[nt][1] = __float_as_uint(Blo[(kb + tig + 4) * PB + cc]);
            }
            // product-major: same-acc mmas are 8 apart
#pragma unroll
            for (int mt = 0; mt < 2; mt++)
#pragma unroll
                for (int nt = 0; nt < 4; nt++) mma_tf32(acc[mt][nt], ah[mt], bh[nt]);
#pragma unroll
            for (int mt = 0; mt < 2; mt++)
#pragma unroll
                for (int nt = 0; nt < 4; nt++) mma_tf32(acc[mt][nt], ah[mt], bl[nt]);
#pragma unroll
            for (int mt = 0; mt < 2; mt++)
#pragma unroll
                for (int nt = 0; nt < 4; nt++) mma_tf32(acc[mt][nt], al[mt], bh[nt]);
        }
        __syncthreads();
    }

    // ---------- epilogue ----------
#pragma unroll
    for (int mt = 0; mt < 2; mt++) {
        long long r0 = bm + wm + (mt << 4) + gid;
#pragma unroll
        for (int nt = 0; nt < 4; nt++) {
            long long cc = bn + wn + (nt << 3) + (tig << 1);
            *reinterpret_cast<float2*>(Cb + r0 * ldC + cc)       = make_float2(acc[mt][nt][0], acc[mt][nt][1]);
            *reinterpret_cast<float2*>(Cb + (r0 + 8) * ldC + cc) = make_float2(acc[mt][nt][2], acc[mt][nt][3]);
        }
    }
}

// ---------------- softmax over last dim ----------------
__global__ void __launch_bounds__(256)
softmax_kernel(float* __restrict__ S, int N)
{
    float* row = S + (long long)blockIdx.x * N;
    const int tid = threadIdx.x;
    __shared__ float red[256];

    float m = -3.4e38f;
    for (int j = tid; j < N; j += 256) m = fmaxf(m, row[j]);
    red[tid] = m;
    __syncthreads();
    for (int s = 128; s > 0; s >>= 1) {
        if (tid < s) red[tid] = fmaxf(red[tid], red[tid + s]);
        __syncthreads();
    }
    m = red[0];
    __syncthreads();

    float sum = 0.0f;
    for (int j = tid; j < N; j += 256) {
        float e = __expf(row[j] - m);
        row[j] = e;
        sum += e;
    }
    red[tid] = sum;
    __syncthreads();
    for (int s = 128; s > 0; s >>= 1) {
        if (tid < s) red[tid] += red[tid + s];
        __syncthreads();
    }
    float inv = 1.0f / red[0];
    __syncthreads();
    for (int j = tid; j < N; j += 256) row[j] *= inv;
}

extern "C" void kernel_launch(void* const* d_in, const int* in_sizes, int n_in,
                              void* d_out, int out_size)
{
    const float* x   = (const float*)d_in[0];  // [B, D, N]
    const float* W_Q = (const float*)d_in[1];  // [MH, D]
    const float* W_K = (const float*)d_in[2];  // [MH, D]
    const float* W_V = (const float*)d_in[3];  // [MV, D]
    const float* W_O = (const float*)d_in[4];  // [D, MV]
    float*       out = (float*)d_out;          // [B, D, N]

    float *q, *k, *v, *s, *attn;
    cudaGetSymbolAddress((void**)&q,    g_q);
    cudaGetSymbolAddress((void**)&k,    g_k);
    cudaGetSymbolAddress((void**)&v,    g_v);
    cudaGetSymbolAddress((void**)&s,    g_s);
    cudaGetSymbolAddress((void**)&attn, g_attn);

    const size_t smem = SMEM_FLOATS * sizeof(float);
    cudaFuncSetAttribute(gemm_mma<false>, cudaFuncAttributeMaxDynamicSharedMemorySize, (int)smem);
    cudaFuncSetAttribute(gemm_mma<true>,  cudaFuncAttributeMaxDynamicSharedMemorySize, (int)smem);

    const long long xB = (long long)DDIM * NSEQ;
    const long long pB = (long long)MH * NSEQ;
    const long long sB = (long long)NSEQ * NSEQ;

    // QKV projections
    {
        dim3 g(NSEQ / 64, MH / 128, BATCH);
        gemm_mma<false><<<g, 256, smem>>>(W_Q, x, q, DDIM, DDIM, NSEQ, NSEQ, 0, xB, pB);
        gemm_mma<false><<<g, 256, smem>>>(W_K, x, k, DDIM, DDIM, NSEQ, NSEQ, 0, xB, pB);
        gemm_mma<false><<<g, 256, smem>>>(W_V, x, v, DDIM, DDIM, NSEQ, NSEQ, 0, xB, pB);
    }
    // scores[i,j] = sum_h k[h,i] * q[h,j]   (A = k, m-contiguous -> TRANS_A)
    {
        dim3 g(NSEQ / 64, NSEQ / 128, BATCH);
        gemm_mma<true><<<g, 256, smem>>>(k, q, s, MH, NSEQ, NSEQ, NSEQ, pB, pB, sB);
    }
    softmax_kernel<<<BATCH * NSEQ, 256>>>(s, NSEQ);
    // attn[v,j] = sum_i V[v,i] * S[i,j]
    {
        dim3 g(NSEQ / 64, MV / 128, BATCH);
        gemm_mma<false><<<g, 256, smem>>>(v, s, attn, NSEQ, NSEQ, NSEQ, NSEQ, pB, sB, pB);
    }
    // out[d,j] = sum_v W_O[d,v] * attn[v,j]
    {
        dim3 g(NSEQ / 64, DDIM / 128, BATCH);
        gemm_mma<false><<<g, 256, smem>>>(W_O, attn, out, MV, MV, NSEQ, NSEQ, 0, pB, xB);
    }
}